// round 1
// baseline (speedup 1.0000x reference)
#include <cuda_runtime.h>
#include <math.h>

// Problem constants (shapes fixed by the dataset)
#define BB 32
#define AA 3
#define HH 160
#define WW 160
#define HW 25600            // H*W
#define NCH 24              // A*8
#define NT 512              // number of targets
#define NUMCLS 3
#define PLANES 96           // B*A conf planes
#define BLOCKS_PER_PLANE 25 // 25600 floats / (256 thr * 4 per thr)
#define NBLK_CONF 2400      // PLANES * BLOCKS_PER_PLANE
#define NBLK_TOTAL 2401
#define TOTAL_CONF 2457600.0  // B*A*H*W

// Per-replay scratch: every slot is written unconditionally each launch,
// so no zeroing pass is needed and the kernel stays graph-replay safe.
__device__ float g_s2[NBLK_CONF];
__device__ float g_misc[4]; // box_sum, cls_sum, conf_corr, n

__device__ __forceinline__ float sigf(float x) {
    return __fdividef(1.0f, 1.0f + __expf(-x));
}

__device__ __forceinline__ float warpSum(float v) {
    #pragma unroll
    for (int o = 16; o > 0; o >>= 1) v += __shfl_down_sync(0xffffffffu, v, o);
    return v;
}

__global__ __launch_bounds__(256) void loss_main(const float* __restrict__ pred,
                                                 const float* __restrict__ targets) {
    const int tid  = threadIdx.x;
    const int lane = tid & 31;
    const int warp = tid >> 5;

    if (blockIdx.x < NBLK_CONF) {
        // ---- Dense conf pass: sum of sigmoid(conf)^2 over one 1024-float chunk ----
        const int plane = blockIdx.x / BLOCKS_PER_PLANE;   // 0..95
        const int chunk = blockIdx.x % BLOCKS_PER_PLANE;   // 0..24
        const int b = plane / AA;
        const int a = plane % AA;
        const float* base = pred + (size_t)(b * NCH + a * 8 + 4) * HW + chunk * 1024;

        float4 v = reinterpret_cast<const float4*>(base)[tid];
        float acc = 0.0f;
        #pragma unroll
        for (int k = 0; k < 4; k++) {
            float x = (&v.x)[k];
            float s = sigf(x);
            acc = fmaf(s, s, acc);
        }

        __shared__ float sh[8];
        float w = warpSum(acc);
        if (lane == 0) sh[warp] = w;
        __syncthreads();
        if (warp == 0) {
            float t = (lane < 8) ? sh[lane] : 0.0f;
            t = warpSum(t);
            if (lane == 0) g_s2[blockIdx.x] = t;
        }
    } else {
        // ---- Sparse target pass: box/cls losses + conf mask correction ----
        float box = 0.0f, cls = 0.0f, corr = 0.0f, n = 0.0f;

        for (int i = tid; i < NT; i += 256) {
            const float* t = targets + i * 6;
            const int   b  = (int)t[0];
            const int   c  = (int)t[1];
            const float tx = t[2], ty = t[3], tw = t[4], th = t[5];
            const int gx = (int)(tx * (float)WW);
            const int gy = (int)(ty * (float)HH);
            // reference "valid" is gx<W & gy<H; negative indices get dropped by
            // the scatter, so require full in-bounds for any contribution.
            if (gx >= 0 && gx < WW && gy >= 0 && gy < HH) {
                const int hw = gy * WW + gx;
                #pragma unroll
                for (int a = 0; a < AA; a++) {
                    const float* p = pred + (size_t)(b * NCH + a * 8) * HW + hw;
                    const float s0 = sigf(p[0]);
                    const float s1 = sigf(p[HW]);
                    const float e2 = expf(p[2 * HW]);
                    const float e3 = expf(p[3 * HW]);
                    float d;
                    d = s0 - tx; box = fmaf(d, d, box);
                    d = s1 - ty; box = fmaf(d, d, box);
                    d = e2 - tw; box = fmaf(d, d, box);
                    d = e3 - th; box = fmaf(d, d, box);
                    // mask correction for the dense pass: (s-1)^2 - s^2 = 1 - 2s
                    corr += 1.0f - 2.0f * sigf(p[4 * HW]);
                    #pragma unroll
                    for (int k = 0; k < NUMCLS; k++) {
                        const float s  = sigf(p[(5 + k) * HW]);
                        const float tc = (k == c) ? 1.0f : 0.0f; // c>=NUMCLS -> all-zero target (drop)
                        d = s - tc; cls = fmaf(d, d, cls);
                    }
                    n += 1.0f;
                }
            }
        }

        __shared__ float sb[8], sc[8], sr[8], sn[8];
        box = warpSum(box); cls = warpSum(cls); corr = warpSum(corr); n = warpSum(n);
        if (lane == 0) { sb[warp] = box; sc[warp] = cls; sr[warp] = corr; sn[warp] = n; }
        __syncthreads();
        if (warp == 0) {
            float vb = (lane < 8) ? sb[lane] : 0.0f;
            float vc = (lane < 8) ? sc[lane] : 0.0f;
            float vr = (lane < 8) ? sr[lane] : 0.0f;
            float vn = (lane < 8) ? sn[lane] : 0.0f;
            vb = warpSum(vb); vc = warpSum(vc); vr = warpSum(vr); vn = warpSum(vn);
            if (lane == 0) {
                g_misc[0] = vb;
                g_misc[1] = vc;
                g_misc[2] = vr;
                g_misc[3] = vn;
            }
        }
    }
}

__global__ __launch_bounds__(256) void loss_finalize(float* __restrict__ out) {
    const int tid  = threadIdx.x;
    const int lane = tid & 31;
    const int warp = tid >> 5;

    double acc = 0.0;
    for (int i = tid; i < NBLK_CONF; i += 256) acc += (double)g_s2[i];
    #pragma unroll
    for (int o = 16; o > 0; o >>= 1) acc += __shfl_down_sync(0xffffffffu, acc, o);

    __shared__ double sh[8];
    if (lane == 0) sh[warp] = acc;
    __syncthreads();
    if (tid == 0) {
        double s2 = 0.0;
        #pragma unroll
        for (int w = 0; w < 8; w++) s2 += sh[w];

        const double box  = (double)g_misc[0];
        const double cls  = (double)g_misc[1];
        const double corr = (double)g_misc[2];
        const double n    = (double)g_misc[3];

        const double loss_conf = (s2 + corr) / TOTAL_CONF;
        const double loss_box  = box / (n * 4.0);
        const double loss_cls  = cls / (n * (double)NUMCLS);
        out[0] = (float)(5.0 * loss_box + loss_conf + loss_cls);
    }
}

extern "C" void kernel_launch(void* const* d_in, const int* in_sizes, int n_in,
                              void* d_out, int out_size) {
    const float* pred    = (const float*)d_in[0];
    const float* targets = (const float*)d_in[1];
    float* out = (float*)d_out;

    loss_main<<<NBLK_TOTAL, 256>>>(pred, targets);
    loss_finalize<<<1, 256>>>(out);
}

// round 2
// speedup vs baseline: 1.0260x; 1.0260x over previous
#include <cuda_runtime.h>
#include <math.h>

// Problem constants (shapes fixed by the dataset)
#define BB 32
#define AA 3
#define HH 160
#define WW 160
#define HW 25600              // H*W
#define HW4 6400              // float4s per plane
#define NCH 24                // A*8
#define NT 512                // number of targets
#define NUMCLS 3
#define NBLK_CONF 600         // 600 blocks * 256 thr * 4 float4 = 2,457,600 floats
#define NBLK_TOTAL 601
#define TOTAL_CONF 2457600.0  // B*A*H*W

// Per-replay scratch: every g_s2/g_misc slot is written unconditionally each
// launch; g_count is reset to 0 by the finalizing block -> graph-replay safe.
__device__ float g_s2[NBLK_CONF];
__device__ float g_misc[4];   // box_sum, cls_sum, conf_corr, n
__device__ int   g_count = 0;

__device__ __forceinline__ float sigf(float x) {
    return __fdividef(1.0f, 1.0f + __expf(-x));
}

__device__ __forceinline__ float warpSum(float v) {
    #pragma unroll
    for (int o = 16; o > 0; o >>= 1) v += __shfl_down_sync(0xffffffffu, v, o);
    return v;
}

__global__ __launch_bounds__(256) void loss_fused(const float* __restrict__ pred,
                                                  const float* __restrict__ targets,
                                                  float* __restrict__ out) {
    const int tid  = threadIdx.x;
    const int lane = tid & 31;
    const int warp = tid >> 5;
    __shared__ float sh[8];
    __shared__ bool  isLast;

    if (blockIdx.x < NBLK_CONF) {
        // ---- Dense conf pass: sum sigmoid(conf)^2, 4 independent float4s/thread ----
        float acc = 0.0f;
        const int g0 = blockIdx.x * 1024 + tid;   // float4 index, stride 256 for k
        #pragma unroll
        for (int k = 0; k < 4; k++) {
            const int g     = g0 + k * 256;
            const int plane = g / HW4;            // 0..95  (b*3+a)
            const int off   = g - plane * HW4;    // float4 offset within plane
            const int b = plane / AA;
            const int a = plane - b * AA;
            const float4* base = reinterpret_cast<const float4*>(
                pred + (size_t)(b * NCH + a * 8 + 4) * HW);
            float4 v = base[off];
            #pragma unroll
            for (int j = 0; j < 4; j++) {
                float s = sigf((&v.x)[j]);
                acc = fmaf(s, s, acc);
            }
        }

        float w = warpSum(acc);
        if (lane == 0) sh[warp] = w;
        __syncthreads();
        if (warp == 0) {
            float t = (lane < 8) ? sh[lane] : 0.0f;
            t = warpSum(t);
            if (lane == 0) g_s2[blockIdx.x] = t;
        }
    } else {
        // ---- Sparse target pass: box/cls losses + conf mask correction ----
        float box = 0.0f, cls = 0.0f, corr = 0.0f, n = 0.0f;

        for (int i = tid; i < NT; i += 256) {
            const float* t = targets + i * 6;
            const int   b  = (int)t[0];
            const int   c  = (int)t[1];
            const float tx = t[2], ty = t[3], tw = t[4], th = t[5];
            const int gx = (int)(tx * (float)WW);
            const int gy = (int)(ty * (float)HH);
            if (gx >= 0 && gx < WW && gy >= 0 && gy < HH) {
                const int hw = gy * WW + gx;
                #pragma unroll
                for (int a = 0; a < AA; a++) {
                    const float* p = pred + (size_t)(b * NCH + a * 8) * HW + hw;
                    const float s0 = sigf(p[0]);
                    const float s1 = sigf(p[HW]);
                    const float e2 = expf(p[2 * HW]);
                    const float e3 = expf(p[3 * HW]);
                    float d;
                    d = s0 - tx; box = fmaf(d, d, box);
                    d = s1 - ty; box = fmaf(d, d, box);
                    d = e2 - tw; box = fmaf(d, d, box);
                    d = e3 - th; box = fmaf(d, d, box);
                    // dense-pass mask correction: (s-1)^2 - s^2 = 1 - 2s
                    corr += 1.0f - 2.0f * sigf(p[4 * HW]);
                    #pragma unroll
                    for (int k = 0; k < NUMCLS; k++) {
                        const float s  = sigf(p[(5 + k) * HW]);
                        const float tc = (k == c) ? 1.0f : 0.0f; // c>=NUMCLS -> all-zero (drop)
                        d = s - tc; cls = fmaf(d, d, cls);
                    }
                    n += 1.0f;
                }
            }
        }

        __shared__ float sb[8], sc[8], sr[8], sn[8];
        box = warpSum(box); cls = warpSum(cls); corr = warpSum(corr); n = warpSum(n);
        if (lane == 0) { sb[warp] = box; sc[warp] = cls; sr[warp] = corr; sn[warp] = n; }
        __syncthreads();
        if (warp == 0) {
            float vb = (lane < 8) ? sb[lane] : 0.0f;
            float vc = (lane < 8) ? sc[lane] : 0.0f;
            float vr = (lane < 8) ? sr[lane] : 0.0f;
            float vn = (lane < 8) ? sn[lane] : 0.0f;
            vb = warpSum(vb); vc = warpSum(vc); vr = warpSum(vr); vn = warpSum(vn);
            if (lane == 0) {
                g_misc[0] = vb; g_misc[1] = vc; g_misc[2] = vr; g_misc[3] = vn;
            }
        }
    }

    // ---- Last-block-standing finalize (threadFenceReduction pattern) ----
    __threadfence();
    if (tid == 0) {
        int ticket = atomicAdd(&g_count, 1);
        isLast = (ticket == NBLK_TOTAL - 1);
    }
    __syncthreads();

    if (isLast) {
        __threadfence();  // acquire all partials
        double acc = 0.0;
        for (int i = tid; i < NBLK_CONF; i += 256) acc += (double)g_s2[i];
        #pragma unroll
        for (int o = 16; o > 0; o >>= 1) acc += __shfl_down_sync(0xffffffffu, acc, o);

        __shared__ double dsh[8];
        if (lane == 0) dsh[warp] = acc;
        __syncthreads();
        if (tid == 0) {
            double s2 = 0.0;
            #pragma unroll
            for (int w = 0; w < 8; w++) s2 += dsh[w];

            const double box  = (double)g_misc[0];
            const double cls  = (double)g_misc[1];
            const double corr = (double)g_misc[2];
            const double n    = (double)g_misc[3];

            const double loss_conf = (s2 + corr) / TOTAL_CONF;
            const double loss_box  = box / (n * 4.0);
            const double loss_cls  = cls / (n * (double)NUMCLS);
            out[0] = (float)(5.0 * loss_box + loss_conf + loss_cls);

            g_count = 0;  // reset for next graph replay
        }
    }
}

extern "C" void kernel_launch(void* const* d_in, const int* in_sizes, int n_in,
                              void* d_out, int out_size) {
    const float* pred    = (const float*)d_in[0];
    const float* targets = (const float*)d_in[1];
    float* out = (float*)d_out;

    loss_fused<<<NBLK_TOTAL, 256>>>(pred, targets, out);
}

// round 3
// speedup vs baseline: 1.4800x; 1.4425x over previous
#include <cuda_runtime.h>
#include <math.h>

// Problem constants (shapes fixed by the dataset)
#define BB 32
#define AA 3
#define HH 160
#define WW 160
#define HW 25600              // H*W
#define HW4 6400              // float4s per plane
#define NCH 24                // A*8
#define NT 512                // number of targets
#define NUMCLS 3
#define NBLK_DENSE 96         // one block per conf plane (b*3+a)
#define NBLK_SPARSE 6         // 6*256 = 1536 = NT*AA pairs, one per thread
#define NBLK_TOTAL (NBLK_DENSE + NBLK_SPARSE)
#define ITERS 25              // float4s per thread in dense pass (6400/256)
#define TOTAL_CONF 2457600.0  // B*A*H*W

// Per-replay scratch: every slot written unconditionally each launch; g_count
// reset by the finalizing block -> graph-replay safe, no zeroing kernel.
__device__ float g_s2[NBLK_DENSE];
__device__ float g_sp[NBLK_SPARSE * 4];  // box, cls, corr, n per sparse block
__device__ int   g_count = 0;

__device__ __forceinline__ float sigf(float x) {
    return __fdividef(1.0f, 1.0f + __expf(-x));
}

__device__ __forceinline__ float warpSum(float v) {
    #pragma unroll
    for (int o = 16; o > 0; o >>= 1) v += __shfl_down_sync(0xffffffffu, v, o);
    return v;
}

__global__ __launch_bounds__(256) void loss_fused(const float* __restrict__ pred,
                                                  const float* __restrict__ targets,
                                                  float* __restrict__ out) {
    const int tid  = threadIdx.x;
    const int lane = tid & 31;
    const int warp = tid >> 5;
    __shared__ float sh[8];
    __shared__ bool  isLast;

    if (blockIdx.x < NBLK_DENSE) {
        // ---- Dense conf pass: one plane per block, 25 float4s per thread ----
        const int plane = blockIdx.x;            // b*3 + a
        const int b = plane / AA;
        const int a = plane - b * AA;
        const float4* base = reinterpret_cast<const float4*>(
            pred + (size_t)(b * NCH + a * 8 + 4) * HW);

        float acc = 0.0f;
        #pragma unroll
        for (int k = 0; k < ITERS; k++) {
            float4 v = base[tid + k * 256];
            #pragma unroll
            for (int j = 0; j < 4; j++) {
                float s = sigf((&v.x)[j]);
                acc = fmaf(s, s, acc);
            }
        }

        float w = warpSum(acc);
        if (lane == 0) sh[warp] = w;
        __syncthreads();
        if (warp == 0) {
            float t = (lane < 8) ? sh[lane] : 0.0f;
            t = warpSum(t);
            if (lane == 0) g_s2[blockIdx.x] = t;
        }
    } else {
        // ---- Sparse pass: exactly one (target, anchor) pair per thread ----
        const int sp   = blockIdx.x - NBLK_DENSE;       // 0..5
        const int pair = sp * 256 + tid;                // 0..1535
        const int i    = pair & 511;                    // target index (coalesced)
        const int a    = pair >> 9;                     // anchor 0..2

        float box = 0.0f, cls = 0.0f, corr = 0.0f, n = 0.0f;

        const float* t = targets + i * 6;
        const int   b  = (int)t[0];
        const int   c  = (int)t[1];
        const float tx = t[2], ty = t[3], tw = t[4], th = t[5];
        const int gx = (int)(tx * (float)WW);
        const int gy = (int)(ty * (float)HH);
        if (gx >= 0 && gx < WW && gy >= 0 && gy < HH) {
            const int hw = gy * WW + gx;
            const float* p = pred + (size_t)(b * NCH + a * 8) * HW + hw;
            // 8 independent scattered loads (MLP=8, single DRAM batch)
            const float x0 = p[0];
            const float x1 = p[HW];
            const float x2 = p[2 * HW];
            const float x3 = p[3 * HW];
            const float x4 = p[4 * HW];
            const float x5 = p[5 * HW];
            const float x6 = p[6 * HW];
            const float x7 = p[7 * HW];

            float d;
            d = sigf(x0) - tx; box = fmaf(d, d, box);
            d = sigf(x1) - ty; box = fmaf(d, d, box);
            d = __expf(x2) * 1.0f; d = expf(x2) - tw; box = fmaf(d, d, box);
            d = expf(x3) - th; box = fmaf(d, d, box);
            corr = 1.0f - 2.0f * sigf(x4);   // (s-1)^2 - s^2 for masked cells
            d = sigf(x5) - ((c == 0) ? 1.0f : 0.0f); cls = fmaf(d, d, cls);
            d = sigf(x6) - ((c == 1) ? 1.0f : 0.0f); cls = fmaf(d, d, cls);
            d = sigf(x7) - ((c == 2) ? 1.0f : 0.0f); cls = fmaf(d, d, cls);
            n = 1.0f;
        }

        __shared__ float sb[8], sc[8], sr[8], sn[8];
        box = warpSum(box); cls = warpSum(cls); corr = warpSum(corr); n = warpSum(n);
        if (lane == 0) { sb[warp] = box; sc[warp] = cls; sr[warp] = corr; sn[warp] = n; }
        __syncthreads();
        if (warp == 0) {
            float vb = (lane < 8) ? sb[lane] : 0.0f;
            float vc = (lane < 8) ? sc[lane] : 0.0f;
            float vr = (lane < 8) ? sr[lane] : 0.0f;
            float vn = (lane < 8) ? sn[lane] : 0.0f;
            vb = warpSum(vb); vc = warpSum(vc); vr = warpSum(vr); vn = warpSum(vn);
            if (lane == 0) {
                g_sp[sp * 4 + 0] = vb;
                g_sp[sp * 4 + 1] = vc;
                g_sp[sp * 4 + 2] = vr;
                g_sp[sp * 4 + 3] = vn;
            }
        }
    }

    // ---- Last-block-standing finalize ----
    __threadfence();
    if (tid == 0) {
        int ticket = atomicAdd(&g_count, 1);
        isLast = (ticket == NBLK_TOTAL - 1);
    }
    __syncthreads();

    if (isLast) {
        __threadfence();  // acquire all partials

        // 96 dense partials: one per thread (tid < 96), then reduce in double.
        double acc = (tid < NBLK_DENSE) ? (double)g_s2[tid] : 0.0;
        #pragma unroll
        for (int o = 16; o > 0; o >>= 1) acc += __shfl_down_sync(0xffffffffu, acc, o);

        __shared__ double dsh[8];
        if (lane == 0) dsh[warp] = acc;
        __syncthreads();
        if (tid == 0) {
            double s2 = 0.0;
            #pragma unroll
            for (int w = 0; w < 8; w++) s2 += dsh[w];

            double box = 0.0, cls = 0.0, corr = 0.0, n = 0.0;
            #pragma unroll
            for (int s = 0; s < NBLK_SPARSE; s++) {
                box  += (double)g_sp[s * 4 + 0];
                cls  += (double)g_sp[s * 4 + 1];
                corr += (double)g_sp[s * 4 + 2];
                n    += (double)g_sp[s * 4 + 3];
            }

            const double loss_conf = (s2 + corr) / TOTAL_CONF;
            const double loss_box  = box / (n * 4.0);
            const double loss_cls  = cls / (n * (double)NUMCLS);
            out[0] = (float)(5.0 * loss_box + loss_conf + loss_cls);

            g_count = 0;  // reset for next graph replay
        }
    }
}

extern "C" void kernel_launch(void* const* d_in, const int* in_sizes, int n_in,
                              void* d_out, int out_size) {
    const float* pred    = (const float*)d_in[0];
    const float* targets = (const float*)d_in[1];
    float* out = (float*)d_out;

    loss_fused<<<NBLK_TOTAL, 256>>>(pred, targets, out);
}

// round 4
// speedup vs baseline: 1.4837x; 1.0025x over previous
#include <cuda_runtime.h>
#include <math.h>

// Problem constants (shapes fixed by the dataset)
#define BB 32
#define AA 3
#define HH 160
#define WW 160
#define HW 25600              // H*W
#define HW4 6400              // float4s per plane
#define NCH 24                // A*8
#define NT 512                // number of targets
#define NUMCLS 3
#define CHUNKS 5              // chunks per conf plane
#define CHUNK4 1280           // float4s per chunk (256 thr * 5)
#define NBLK_DENSE 480        // 96 planes * 5 chunks
#define NBLK_SPARSE 6         // 6*256 = 1536 = NT*AA pairs, one per thread
#define NBLK_TOTAL (NBLK_DENSE + NBLK_SPARSE)
#define TOTAL_CONF 2457600.0  // B*A*H*W

// Per-replay scratch: every slot written unconditionally each launch; g_count
// reset by the finalizing block -> graph-replay safe, no zeroing kernel.
__device__ float g_s2[NBLK_DENSE];
__device__ float g_sp[NBLK_SPARSE * 4];  // box, cls, corr, n per sparse block
__device__ int   g_count = 0;

__device__ __forceinline__ float sigf(float x) {
    return __fdividef(1.0f, 1.0f + __expf(-x));
}

__device__ __forceinline__ float warpSum(float v) {
    #pragma unroll
    for (int o = 16; o > 0; o >>= 1) v += __shfl_down_sync(0xffffffffu, v, o);
    return v;
}

__device__ __forceinline__ float sumSq4(float4 v) {
    float s0 = sigf(v.x), s1 = sigf(v.y), s2 = sigf(v.z), s3 = sigf(v.w);
    float acc = s0 * s0;
    acc = fmaf(s1, s1, acc);
    acc = fmaf(s2, s2, acc);
    acc = fmaf(s3, s3, acc);
    return acc;
}

__global__ __launch_bounds__(256) void loss_fused(const float* __restrict__ pred,
                                                  const float* __restrict__ targets,
                                                  float* __restrict__ out) {
    const int tid  = threadIdx.x;
    const int lane = tid & 31;
    const int warp = tid >> 5;
    __shared__ float sh[8];
    __shared__ bool  isLast;

    if (blockIdx.x < NBLK_DENSE) {
        // ---- Dense conf pass: 5 straight-line float4 loads per thread ----
        const int plane = blockIdx.x / CHUNKS;             // 0..95 (b*3+a)
        const int chunk = blockIdx.x - plane * CHUNKS;     // 0..4
        // conf channel of plane p=(b*3+a) is flat plane index p*8+4
        const float4* base = reinterpret_cast<const float4*>(
            pred + (size_t)(plane * 8 + 4) * HW) + chunk * CHUNK4 + tid;

        // 5 independent loads, front-batched (MLP=5 per thread)
        const float4 v0 = base[0];
        const float4 v1 = base[256];
        const float4 v2 = base[512];
        const float4 v3 = base[768];
        const float4 v4 = base[1024];

        float acc = sumSq4(v0);
        acc += sumSq4(v1);
        acc += sumSq4(v2);
        acc += sumSq4(v3);
        acc += sumSq4(v4);

        float w = warpSum(acc);
        if (lane == 0) sh[warp] = w;
        __syncthreads();
        if (warp == 0) {
            float t = (lane < 8) ? sh[lane] : 0.0f;
            t = warpSum(t);
            if (lane == 0) g_s2[blockIdx.x] = t;
        }
    } else {
        // ---- Sparse pass: exactly one (target, anchor) pair per thread ----
        const int sp   = blockIdx.x - NBLK_DENSE;       // 0..5
        const int pair = sp * 256 + tid;                // 0..1535
        const int i    = pair & 511;                    // target index (coalesced)
        const int a    = pair >> 9;                     // anchor 0..2

        float box = 0.0f, cls = 0.0f, corr = 0.0f, n = 0.0f;

        const float* t = targets + i * 6;
        const int   b  = (int)t[0];
        const int   c  = (int)t[1];
        const float tx = t[2], ty = t[3], tw = t[4], th = t[5];
        const int gx = (int)(tx * (float)WW);
        const int gy = (int)(ty * (float)HH);
        if (gx >= 0 && gx < WW && gy >= 0 && gy < HH) {
            const int hw = gy * WW + gx;
            const float* p = pred + (size_t)(b * NCH + a * 8) * HW + hw;
            // 8 independent scattered loads (MLP=8, single DRAM batch)
            const float x0 = p[0];
            const float x1 = p[HW];
            const float x2 = p[2 * HW];
            const float x3 = p[3 * HW];
            const float x4 = p[4 * HW];
            const float x5 = p[5 * HW];
            const float x6 = p[6 * HW];
            const float x7 = p[7 * HW];

            float d;
            d = sigf(x0) - tx; box = fmaf(d, d, box);
            d = sigf(x1) - ty; box = fmaf(d, d, box);
            d = expf(x2) - tw; box = fmaf(d, d, box);
            d = expf(x3) - th; box = fmaf(d, d, box);
            corr = 1.0f - 2.0f * sigf(x4);   // (s-1)^2 - s^2 for masked cells
            d = sigf(x5) - ((c == 0) ? 1.0f : 0.0f); cls = fmaf(d, d, cls);
            d = sigf(x6) - ((c == 1) ? 1.0f : 0.0f); cls = fmaf(d, d, cls);
            d = sigf(x7) - ((c == 2) ? 1.0f : 0.0f); cls = fmaf(d, d, cls);
            n = 1.0f;
        }

        __shared__ float sb[8], sc[8], sr[8], sn[8];
        box = warpSum(box); cls = warpSum(cls); corr = warpSum(corr); n = warpSum(n);
        if (lane == 0) { sb[warp] = box; sc[warp] = cls; sr[warp] = corr; sn[warp] = n; }
        __syncthreads();
        if (warp == 0) {
            float vb = (lane < 8) ? sb[lane] : 0.0f;
            float vc = (lane < 8) ? sc[lane] : 0.0f;
            float vr = (lane < 8) ? sr[lane] : 0.0f;
            float vn = (lane < 8) ? sn[lane] : 0.0f;
            vb = warpSum(vb); vc = warpSum(vc); vr = warpSum(vr); vn = warpSum(vn);
            if (lane == 0) {
                g_sp[sp * 4 + 0] = vb;
                g_sp[sp * 4 + 1] = vc;
                g_sp[sp * 4 + 2] = vr;
                g_sp[sp * 4 + 3] = vn;
            }
        }
    }

    // ---- Last-block-standing finalize ----
    __threadfence();
    if (tid == 0) {
        int ticket = atomicAdd(&g_count, 1);
        isLast = (ticket == NBLK_TOTAL - 1);
    }
    __syncthreads();

    if (isLast) {
        __threadfence();  // acquire all partials

        // 480 dense partials: 2 loads per thread, reduce in double.
        double acc = (double)g_s2[tid];
        if (tid < NBLK_DENSE - 256) acc += (double)g_s2[tid + 256];
        #pragma unroll
        for (int o = 16; o > 0; o >>= 1) acc += __shfl_down_sync(0xffffffffu, acc, o);

        __shared__ double dsh[8];
        if (lane == 0) dsh[warp] = acc;
        __syncthreads();
        if (tid == 0) {
            double s2 = 0.0;
            #pragma unroll
            for (int w = 0; w < 8; w++) s2 += dsh[w];

            double box = 0.0, cls = 0.0, corr = 0.0, n = 0.0;
            #pragma unroll
            for (int s = 0; s < NBLK_SPARSE; s++) {
                box  += (double)g_sp[s * 4 + 0];
                cls  += (double)g_sp[s * 4 + 1];
                corr += (double)g_sp[s * 4 + 2];
                n    += (double)g_sp[s * 4 + 3];
            }

            const double loss_conf = (s2 + corr) / TOTAL_CONF;
            const double loss_box  = box / (n * 4.0);
            const double loss_cls  = cls / (n * (double)NUMCLS);
            out[0] = (float)(5.0 * loss_box + loss_conf + loss_cls);

            g_count = 0;  // reset for next graph replay
        }
    }
}

extern "C" void kernel_launch(void* const* d_in, const int* in_sizes, int n_in,
                              void* d_out, int out_size) {
    const float* pred    = (const float*)d_in[0];
    const float* targets = (const float*)d_in[1];
    float* out = (float*)d_out;

    loss_fused<<<NBLK_TOTAL, 256>>>(pred, targets, out);
}